// round 5
// baseline (speedup 1.0000x reference)
#include <cuda_runtime.h>
#include <cstdint>
#include <math.h>

#define N_SENTC 256
#define BATCH   512
#define SEQ     128
#define DIM     1024
#define LBL     10331
#define LATD    101
#define DIM2    2048
#define NEGV    (-10000.0f)

// ---------------- scratch (__device__ statics: the allowed scratch path) ----
__device__ float g_C1[(size_t)N_SENTC * SEQ * DIM];  // elmo @ W_ctx_c^T per sentence (134 MB)
__device__ float g_menScore[N_SENTC * SEQ];          // per-sentence mention scores
__device__ float g_ctxScore[BATCH * SEQ];
__device__ float g_final[BATCH * DIM2];              // [men_repr | ctx_repr]
__device__ float g_m2[BATCH * DIM];                  // men_repr @ W_ctx_m^T
__device__ float g_latent[BATCH * LATD];

// ---------------- helpers ---------------------------------------------------
__device__ __forceinline__ float ftanh(float x) {
    // tanh(x) = 1 - 2/(exp(2x)+1); exact limits at +-inf, ~1e-6 rel err
    float e = __expf(2.0f * x);
    return 1.0f - __fdividef(2.0f, e + 1.0f);
}

__device__ __forceinline__ float4 guarded_load4(const float* __restrict__ P, int ld,
                                                int R, int K, int r, int k, bool vecOK) {
    float4 v = make_float4(0.f, 0.f, 0.f, 0.f);
    if (r < R) {
        const float* p = P + (size_t)r * ld + k;
        if (vecOK && (k + 3 < K)) {
            v = *reinterpret_cast<const float4*>(p);
        } else {
            if (k + 0 < K) v.x = p[0];
            if (k + 1 < K) v.y = p[1];
            if (k + 2 < K) v.z = p[2];
            if (k + 3 < K) v.w = p[3];
        }
    }
    return v;
}

__global__ void zero_kernel(float* p, int n) {
    int i = blockIdx.x * blockDim.x + threadIdx.x;
    if (i < n) p[i] = 0.0f;
}

// ---------------- generic C = A * B^T GEMM (A:[M,K] lda, B:[N,K] ldb) -------
// 128x128 tile, BK=8, 256 threads, 8x8 microtile, double-buffered smem.
enum { MODE_STORE = 0, MODE_MEN = 1, MODE_OUT = 2 };

template <int MODE>
__global__ __launch_bounds__(256, 2)
void gemm_tn(const float* __restrict__ A, int lda,
             const float* __restrict__ Bm, int ldb,
             float* __restrict__ C, int ldc,
             int M, int N, int K,
             const float* __restrict__ wo,     // MODE_MEN: output-weight vector [N]
             float* __restrict__ rowAcc,       // MODE_MEN: per-row atomic accumulator [M]
             const float* __restrict__ aux,    // MODE_OUT: OL matrix, same ldc
             const float* __restrict__ scal)   // MODE_OUT: latent_scalar (device)
{
    __shared__ float As[2][8][128];
    __shared__ float Bs[2][8][128];

    const int tid  = threadIdx.x;
    const int m0   = blockIdx.y * 128;
    const int n0   = blockIdx.x * 128;
    const int lrow = tid >> 1;          // 0..127
    const int lk   = (tid & 1) * 4;     // 0 or 4
    const int tx   = tid & 15;
    const int ty   = tid >> 4;
    const bool aVec = ((lda & 3) == 0);
    const bool bVec = ((ldb & 3) == 0);

    float acc[8][8];
#pragma unroll
    for (int i = 0; i < 8; i++)
#pragma unroll
        for (int j = 0; j < 8; j++) acc[i][j] = 0.0f;

    const int nk = (K + 7) >> 3;

    // prologue: tile 0
    {
        float4 av = guarded_load4(A,  lda, M, K, m0 + lrow, lk, aVec);
        float4 bv = guarded_load4(Bm, ldb, N, K, n0 + lrow, lk, bVec);
        As[0][lk + 0][lrow] = av.x; As[0][lk + 1][lrow] = av.y;
        As[0][lk + 2][lrow] = av.z; As[0][lk + 3][lrow] = av.w;
        Bs[0][lk + 0][lrow] = bv.x; Bs[0][lk + 1][lrow] = bv.y;
        Bs[0][lk + 2][lrow] = bv.z; Bs[0][lk + 3][lrow] = bv.w;
    }
    __syncthreads();

    int buf = 0;
    for (int kt = 0; kt < nk; kt++) {
        float4 na = make_float4(0.f, 0.f, 0.f, 0.f);
        float4 nb = make_float4(0.f, 0.f, 0.f, 0.f);
        if (kt + 1 < nk) {
            na = guarded_load4(A,  lda, M, K, m0 + lrow, (kt + 1) * 8 + lk, aVec);
            nb = guarded_load4(Bm, ldb, N, K, n0 + lrow, (kt + 1) * 8 + lk, bVec);
        }
#pragma unroll
        for (int kk = 0; kk < 8; kk++) {
            float4 a0 = *reinterpret_cast<const float4*>(&As[buf][kk][ty * 4]);
            float4 a1 = *reinterpret_cast<const float4*>(&As[buf][kk][64 + ty * 4]);
            float4 b0 = *reinterpret_cast<const float4*>(&Bs[buf][kk][tx * 4]);
            float4 b1 = *reinterpret_cast<const float4*>(&Bs[buf][kk][64 + tx * 4]);
            float ar[8] = {a0.x, a0.y, a0.z, a0.w, a1.x, a1.y, a1.z, a1.w};
            float br[8] = {b0.x, b0.y, b0.z, b0.w, b1.x, b1.y, b1.z, b1.w};
#pragma unroll
            for (int i = 0; i < 8; i++)
#pragma unroll
                for (int j = 0; j < 8; j++)
                    acc[i][j] = fmaf(ar[i], br[j], acc[i][j]);
        }
        if (kt + 1 < nk) {
            buf ^= 1;
            As[buf][lk + 0][lrow] = na.x; As[buf][lk + 1][lrow] = na.y;
            As[buf][lk + 2][lrow] = na.z; As[buf][lk + 3][lrow] = na.w;
            Bs[buf][lk + 0][lrow] = nb.x; Bs[buf][lk + 1][lrow] = nb.y;
            Bs[buf][lk + 2][lrow] = nb.z; Bs[buf][lk + 3][lrow] = nb.w;
            __syncthreads();
        }
    }

    int rofs[8], cofs[8];
#pragma unroll
    for (int i = 0; i < 4; i++) {
        rofs[i]     = ty * 4 + i;
        rofs[i + 4] = 64 + ty * 4 + i;
        cofs[i]     = tx * 4 + i;
        cofs[i + 4] = 64 + tx * 4 + i;
    }

    if (MODE == MODE_STORE) {
#pragma unroll
        for (int i = 0; i < 8; i++) {
            int m = m0 + rofs[i];
            if (m < M) {
                size_t base = (size_t)m * ldc;
#pragma unroll
                for (int j = 0; j < 8; j++) {
                    int n = n0 + cofs[j];
                    if (n < N) C[base + n] = acc[i][j];
                }
            }
        }
    } else if (MODE == MODE_OUT) {
        float ls = *scal;
#pragma unroll
        for (int i = 0; i < 8; i++) {
            int m = m0 + rofs[i];
            if (m < M) {
                size_t base = (size_t)m * ldc;
#pragma unroll
                for (int j = 0; j < 8; j++) {
                    int n = n0 + cofs[j];
                    if (n < N) C[base + n] = acc[i][j] + ls * aux[base + n];
                }
            }
        }
    } else {  // MODE_MEN: rowScore[m] += sum_n tanh(acc) * wo[n]
        float rsum[8];
#pragma unroll
        for (int i = 0; i < 8; i++) rsum[i] = 0.0f;
#pragma unroll
        for (int i = 0; i < 8; i++) {
#pragma unroll
            for (int j = 0; j < 8; j++) {
                int n = n0 + cofs[j];
                float w = (n < N) ? wo[n] : 0.0f;
                rsum[i] += ftanh(acc[i][j]) * w;
            }
        }
        // reduce across the 16 tx lanes (rows depend only on ty)
#pragma unroll
        for (int off = 8; off > 0; off >>= 1)
#pragma unroll
            for (int i = 0; i < 8; i++)
                rsum[i] += __shfl_xor_sync(0xffffffffu, rsum[i], off);
        if (tx == 0) {
#pragma unroll
            for (int i = 0; i < 8; i++) {
                int m = m0 + rofs[i];
                if (m < M) atomicAdd(&rowAcc[m], rsum[i]);
            }
        }
    }
}

// ---------------- masked softmax over S + weighted sum over x ---------------
// One block per b (256 threads). Writes repr into outBase[b*DIM2 .. +1023].
__global__ void attn_kernel(const float* __restrict__ elmo,
                            const int* __restrict__ gathers,
                            const float* __restrict__ scores,
                            const float* __restrict__ mask,
                            int gatherScores,
                            float* __restrict__ outBase)
{
    int b = blockIdx.x;
    int tid = threadIdx.x;
    __shared__ float attn_s[SEQ];
    __shared__ float red[8];
    int g = gathers[b];

    float sc = -1e30f;
    if (tid < SEQ) {
        float raw = gatherScores ? scores[g * SEQ + tid] : scores[b * SEQ + tid];
        sc = raw + (1.0f - mask[b * SEQ + tid]) * NEGV;
    }
    // block max (only warps 0..3 hold data)
    float v = sc;
#pragma unroll
    for (int off = 16; off > 0; off >>= 1)
        v = fmaxf(v, __shfl_xor_sync(0xffffffffu, v, off));
    if ((tid & 31) == 0) red[tid >> 5] = v;
    __syncthreads();
    float mx = fmaxf(fmaxf(red[0], red[1]), fmaxf(red[2], red[3]));
    __syncthreads();

    float e = (tid < SEQ) ? __expf(sc - mx) : 0.0f;
    v = e;
#pragma unroll
    for (int off = 16; off > 0; off >>= 1)
        v += __shfl_xor_sync(0xffffffffu, v, off);
    if ((tid & 31) == 0) red[tid >> 5] = v;
    __syncthreads();
    float sum = red[0] + red[1] + red[2] + red[3];
    if (tid < SEQ) attn_s[tid] = e / sum;
    __syncthreads();

    // repr[d] = sum_s attn[s] * x[s,d]; thread owns floats 4*tid..4*tid+3
    const float4* xr = reinterpret_cast<const float4*>(elmo + (size_t)g * SEQ * DIM);
    float4 accv = make_float4(0.f, 0.f, 0.f, 0.f);
#pragma unroll 4
    for (int s = 0; s < SEQ; s++) {
        float a = attn_s[s];
        float4 x = xr[(size_t)s * (DIM / 4) + tid];
        accv.x = fmaf(a, x.x, accv.x);
        accv.y = fmaf(a, x.y, accv.y);
        accv.z = fmaf(a, x.z, accv.z);
        accv.w = fmaf(a, x.w, accv.w);
    }
    reinterpret_cast<float4*>(outBase + (size_t)b * DIM2)[tid] = accv;
}

// ---------------- fused context score --------------------------------------
// score[b,s] = sum_e wo[e]*tanh(C1[g,s,e] + m2[b,e] + dist[b,s]*wd[e])
__global__ void ctx_score_kernel(const int* __restrict__ gathers,
                                 const float* __restrict__ dist,
                                 const float* __restrict__ wd,
                                 const float* __restrict__ wo)
{
    int b = blockIdx.x;
    int tid = threadIdx.x;   // 256 threads, each owns 4 e's
    __shared__ float red[8];
    int g = gathers[b];
    int e0 = tid * 4;
    float4 m2v = *reinterpret_cast<const float4*>(&g_m2[(size_t)b * DIM + e0]);
    float4 wdv = *reinterpret_cast<const float4*>(&wd[e0]);
    float4 wov = *reinterpret_cast<const float4*>(&wo[e0]);
    const float4* c1 = reinterpret_cast<const float4*>(g_C1) + (size_t)g * SEQ * (DIM / 4);

    for (int s = 0; s < SEQ; s++) {
        float dv = dist[b * SEQ + s];
        float4 c = c1[(size_t)s * (DIM / 4) + tid];
        float p = wov.x * ftanh(c.x + m2v.x + dv * wdv.x)
                + wov.y * ftanh(c.y + m2v.y + dv * wdv.y)
                + wov.z * ftanh(c.z + m2v.z + dv * wdv.z)
                + wov.w * ftanh(c.w + m2v.w + dv * wdv.w);
#pragma unroll
        for (int off = 16; off > 0; off >>= 1)
            p += __shfl_xor_sync(0xffffffffu, p, off);
        if ((tid & 31) == 0) red[tid >> 5] = p;
        __syncthreads();
        if (tid == 0) {
            g_ctxScore[b * SEQ + s] =
                red[0] + red[1] + red[2] + red[3] + red[4] + red[5] + red[6] + red[7];
        }
        __syncthreads();
    }
}

// ---------------- latent = final @ W_f2l^T  [B, 101] ------------------------
__global__ void latent_kernel(const float* __restrict__ Wf2l)
{
    int b = blockIdx.x;
    int tid = threadIdx.x;   // 128 threads
    __shared__ float4 sf[DIM2 / 4];
    const float4* fr = reinterpret_cast<const float4*>(&g_final[(size_t)b * DIM2]);
    for (int i = tid; i < DIM2 / 4; i += 128) sf[i] = fr[i];
    __syncthreads();
    if (tid < LATD) {
        const float4* wr = reinterpret_cast<const float4*>(Wf2l + (size_t)tid * DIM2);
        float acc = 0.0f;
#pragma unroll 4
        for (int k = 0; k < DIM2 / 4; k++) {
            float4 w = wr[k];
            float4 f = sf[k];
            acc += w.x * f.x + w.y * f.y + w.z * f.z + w.w * f.w;
        }
        g_latent[b * LATD + tid] = acc;
    }
}

// ---------------- launch -----------------------------------------------------
extern "C" void kernel_launch(void* const* d_in, const int* in_sizes, int n_in,
                              void* d_out, int out_size)
{
    const float* elmo     = (const float*)d_in[0];
    const float* men_mask = (const float*)d_in[1];
    const float* ctx_mask = (const float*)d_in[2];
    const float* dist     = (const float*)d_in[3];
    const int*   gathers  = (const int*)  d_in[4];
    const float* W_men_m  = (const float*)d_in[5];
    const float* W_men_o  = (const float*)d_in[6];
    const float* W_ctx_c  = (const float*)d_in[7];
    const float* W_ctx_m  = (const float*)d_in[8];
    const float* w_ctx_d  = (const float*)d_in[9];
    const float* W_ctx_o  = (const float*)d_in[10];
    const float* W_out    = (const float*)d_in[11];
    const float* W_f2l    = (const float*)d_in[12];
    const float* W_l2l    = (const float*)d_in[13];
    const float* lscal    = (const float*)d_in[14];

    float* out_main = (float*)d_out;                       // outputs [B, L]
    float* out_lat  = out_main + (size_t)BATCH * LBL;      // outputs_latent [B, L]

    float *pC1, *pMS, *pCS, *pFin, *pM2, *pLat;
    cudaGetSymbolAddress((void**)&pC1,  g_C1);
    cudaGetSymbolAddress((void**)&pMS,  g_menScore);
    cudaGetSymbolAddress((void**)&pCS,  g_ctxScore);
    cudaGetSymbolAddress((void**)&pFin, g_final);
    cudaGetSymbolAddress((void**)&pM2,  g_m2);
    cudaGetSymbolAddress((void**)&pLat, g_latent);

    // 1. zero mention-score accumulator (atomicAdd target)
    zero_kernel<<<(N_SENTC * SEQ + 255) / 256, 256>>>(pMS, N_SENTC * SEQ);

    // 2. per-sentence mention scores: fused GEMM (M=32768, N=1024, K=1024)
    gemm_tn<MODE_MEN><<<dim3(8, 256), 256>>>(
        elmo, DIM, W_men_m, DIM, nullptr, 0,
        N_SENTC * SEQ, DIM, DIM, W_men_o, pMS, nullptr, nullptr);

    // 3. C1 = elmo @ W_ctx_c^T per sentence (M=32768, N=1024, K=1024)
    gemm_tn<MODE_STORE><<<dim3(8, 256), 256>>>(
        elmo, DIM, W_ctx_c, DIM, pC1, DIM,
        N_SENTC * SEQ, DIM, DIM, nullptr, nullptr, nullptr, nullptr);

    // 4. mention softmax + men_repr -> final[:, 0:1024]
    attn_kernel<<<BATCH, 256>>>(elmo, gathers, pMS, men_mask, 1, pFin);

    // 5. m2 = men_repr @ W_ctx_m^T (M=512, N=1024, K=1024; lda=2048)
    gemm_tn<MODE_STORE><<<dim3(8, 4), 256>>>(
        pFin, DIM2, W_ctx_m, DIM, pM2, DIM,
        BATCH, DIM, DIM, nullptr, nullptr, nullptr, nullptr);

    // 6. fused context scores
    ctx_score_kernel<<<BATCH, 256>>>(gathers, dist, w_ctx_d, W_ctx_o);

    // 7. context softmax + ctx_repr -> final[:, 1024:2048]
    attn_kernel<<<BATCH, 256>>>(elmo, gathers, pCS, ctx_mask, 0, pFin + DIM);

    // 8. latent = final @ W_f2l^T  [512, 101]
    latent_kernel<<<BATCH, 128>>>(W_f2l);

    // 9. outputs_latent = latent @ W_l2l^T (M=512, N=10331, K=101) -> out_lat
    gemm_tn<MODE_STORE><<<dim3(81, 4), 256>>>(
        pLat, LATD, W_l2l, LATD, out_lat, LBL,
        BATCH, LBL, LATD, nullptr, nullptr, nullptr, nullptr);

    // 10. outputs = final @ W_out^T + latent_scalar * outputs_latent -> out_main
    gemm_tn<MODE_OUT><<<dim3(81, 4), 256>>>(
        pFin, DIM2, W_out, DIM2, out_main, LBL,
        BATCH, LBL, DIM2, nullptr, nullptr, out_lat, lscal);
}

// round 7
// speedup vs baseline: 1.9421x; 1.9421x over previous
#include <cuda_runtime.h>
#include <cuda_bf16.h>
#include <cstdint>
#include <math.h>

#define N_SENTC 256
#define BATCH   512
#define SEQ     128
#define DIM     1024
#define LBL     10331
#define LATD    101
#define DIM2    2048
#define NEGV    (-10000.0f)

// ---------------- scratch -----------------------------------------------------
__device__ float g_C1[(size_t)N_SENTC * SEQ * DIM];  // elmo @ W_ctx_c^T per sentence
__device__ float g_menScore[N_SENTC * SEQ];
__device__ float g_ctxScore[BATCH * SEQ];
__device__ float g_final[BATCH * DIM2];
__device__ float g_m2[BATCH * DIM];
__device__ float g_latent[BATCH * LATD];

// ---------------- helpers -----------------------------------------------------
__device__ __forceinline__ uint32_t smem_to_u32(const void* p) {
    uint32_t a;
    asm("{ .reg .u64 t; cvta.to.shared.u64 t, %1; cvt.u32.u64 %0, t; }" : "=r"(a) : "l"(p));
    return a;
}

__device__ __forceinline__ float ftanh(float x) {
    // precise: tanh(x) = 1 - 2/(exp(2x)+1); ~1e-6 rel err, exact saturation
    float e = __expf(2.0f * x);
    return 1.0f - __fdividef(2.0f, e + 1.0f);
}

__device__ __forceinline__ float4 guarded_load4(const float* __restrict__ P, int ld,
                                                int R, int K, int r, int k, bool vecOK) {
    float4 v = make_float4(0.f, 0.f, 0.f, 0.f);
    if (r < R) {
        const float* p = P + (size_t)r * ld + k;
        if (vecOK && (k + 3 < K)) {
            v = *reinterpret_cast<const float4*>(p);
        } else {
            if (k + 0 < K) v.x = p[0];
            if (k + 1 < K) v.y = p[1];
            if (k + 2 < K) v.z = p[2];
            if (k + 3 < K) v.w = p[3];
        }
    }
    return v;
}

__device__ __forceinline__ void split4(float4 v, uint2& hi, uint2& lo) {
    float x[4] = {v.x, v.y, v.z, v.w};
    unsigned short h[4], l[4];
#pragma unroll
    for (int i = 0; i < 4; i++) {
        __nv_bfloat16 bh = __float2bfloat16(x[i]);
        float r = x[i] - __bfloat162float(bh);
        __nv_bfloat16 bl = __float2bfloat16(r);
        h[i] = __bfloat16_as_ushort(bh);
        l[i] = __bfloat16_as_ushort(bl);
    }
    hi.x = (uint32_t)h[0] | ((uint32_t)h[1] << 16);
    hi.y = (uint32_t)h[2] | ((uint32_t)h[3] << 16);
    lo.x = (uint32_t)l[0] | ((uint32_t)l[1] << 16);
    lo.y = (uint32_t)l[2] | ((uint32_t)l[3] << 16);
}

__global__ void zero_kernel(float* p, int n) {
    int i = blockIdx.x * blockDim.x + threadIdx.x;
    if (i < n) p[i] = 0.0f;
}

// ---------------- warp-mma primitives (baseline PTX, sm_80+) ------------------
__device__ __forceinline__ void ldsm4(uint32_t* r, uint32_t addr) {
    asm volatile("ldmatrix.sync.aligned.m8n8.x4.shared.b16 {%0,%1,%2,%3}, [%4];"
                 : "=r"(r[0]), "=r"(r[1]), "=r"(r[2]), "=r"(r[3]) : "r"(addr));
}
__device__ __forceinline__ void mma16816(float (&c)[4], const uint32_t* a, const uint32_t* b) {
    asm volatile("mma.sync.aligned.m16n8k16.row.col.f32.bf16.bf16.f32 "
                 "{%0,%1,%2,%3}, {%4,%5,%6,%7}, {%8,%9}, {%0,%1,%2,%3};"
                 : "+f"(c[0]), "+f"(c[1]), "+f"(c[2]), "+f"(c[3])
                 : "r"(a[0]), "r"(a[1]), "r"(a[2]), "r"(a[3]), "r"(b[0]), "r"(b[1]));
}

// smem tile: 128 rows x 32 bf16 (64B rows, 4 chunks of 16B, XOR swizzle)
__device__ __forceinline__ uint32_t sw_off(int row, int chunk) {
    return (uint32_t)(row * 64 + (((chunk ^ ((row >> 1) & 3)) & 3) << 4));
}

// stage layout: Ah | Al | Bh | Bl, each 128*64 = 8192 B
#define AH_OFF 0
#define AL_OFF 8192
#define BH_OFF 16384
#define BL_OFF 24576
#define STAGE_BYTES 32768
#define SMEM_GEMM (2 * STAGE_BYTES)

enum { MODE_STORE = 0, MODE_MEN = 1, MODE_OUT = 2 };

// ---------------- split-bf16 3-pass warp-mma GEMM:  C = A * B^T ---------------
// A:[M,K] lda fp32, B:[N,K] ldb fp32. CTA 128x128, BK=32, 256 threads (8 warps).
template <int MODE>
__global__ __launch_bounds__(256, 1)
void gemm_mma(const float* __restrict__ A, int lda,
              const float* __restrict__ Bm, int ldb,
              float* __restrict__ C, int ldc,
              int M, int N, int K,
              const float* __restrict__ wo,     // MODE_MEN
              float* __restrict__ rowAcc,       // MODE_MEN
              const float* __restrict__ aux,    // MODE_OUT
              const float* __restrict__ scal)   // MODE_OUT
{
    extern __shared__ char smem[];
    const uint32_t sb = smem_to_u32(smem);
    const int tid  = threadIdx.x;
    const int lane = tid & 31;
    const int wid  = tid >> 5;
    const int wm0  = (wid >> 2) * 64;   // warp M offset in CTA tile
    const int wn0  = (wid & 3) * 32;    // warp N offset
    const int m0   = blockIdx.y * 128;
    const int n0   = blockIdx.x * 128;
    const bool aVec = ((lda & 3) == 0);
    const bool bVec = ((ldb & 3) == 0);
    const bool fullA = (m0 + 128 <= M);
    const bool fullB = (n0 + 128 <= N);

    float acc[4][4][4];
#pragma unroll
    for (int i = 0; i < 4; i++)
#pragma unroll
        for (int j = 0; j < 4; j++)
#pragma unroll
            for (int q = 0; q < 4; q++) acc[i][j][q] = 0.0f;

    const int nk = (K + 31) >> 5;
    // per-thread gmem->smem tile coordinates: 2 groups of 8 floats each
    const int row0 = (tid + 0)   >> 2, kg0 = (tid + 0)   & 3;
    const int row1 = (tid + 256) >> 2, kg1 = (tid + 256) & 3;

    float4 rA[2][2], rB[2][2];

    // ---- chunk loader (registers) ----
    auto load_chunk = [&](int c) {
        const int kbase = c * 32;
        const bool fullK = (kbase + 32 <= K);
        const int rows[2] = {row0, row1};
        const int kgs[2]  = {kg0, kg1};
#pragma unroll
        for (int it = 0; it < 2; it++) {
            int k = kbase + kgs[it] * 8;
            if (fullA && fullK && aVec) {
                const float* p = A + (size_t)(m0 + rows[it]) * lda + k;
                rA[it][0] = *reinterpret_cast<const float4*>(p);
                rA[it][1] = *reinterpret_cast<const float4*>(p + 4);
            } else {
                rA[it][0] = guarded_load4(A, lda, M, K, m0 + rows[it], k, aVec);
                rA[it][1] = guarded_load4(A, lda, M, K, m0 + rows[it], k + 4, aVec);
            }
            if (fullB && fullK && bVec) {
                const float* p = Bm + (size_t)(n0 + rows[it]) * ldb + k;
                rB[it][0] = *reinterpret_cast<const float4*>(p);
                rB[it][1] = *reinterpret_cast<const float4*>(p + 4);
            } else {
                rB[it][0] = guarded_load4(Bm, ldb, N, K, n0 + rows[it], k, bVec);
                rB[it][1] = guarded_load4(Bm, ldb, N, K, n0 + rows[it], k + 4, bVec);
            }
        }
    };

    auto store_chunk = [&](char* st) {
        const int rows[2] = {row0, row1};
        const int kgs[2]  = {kg0, kg1};
#pragma unroll
        for (int it = 0; it < 2; it++) {
            uint32_t o = sw_off(rows[it], kgs[it]);
            uint2 h0, l0, h1, l1;
            split4(rA[it][0], h0, l0); split4(rA[it][1], h1, l1);
            *reinterpret_cast<uint4*>(st + AH_OFF + o) = make_uint4(h0.x, h0.y, h1.x, h1.y);
            *reinterpret_cast<uint4*>(st + AL_OFF + o) = make_uint4(l0.x, l0.y, l1.x, l1.y);
            split4(rB[it][0], h0, l0); split4(rB[it][1], h1, l1);
            *reinterpret_cast<uint4*>(st + BH_OFF + o) = make_uint4(h0.x, h0.y, h1.x, h1.y);
            *reinterpret_cast<uint4*>(st + BL_OFF + o) = make_uint4(l0.x, l0.y, l1.x, l1.y);
        }
    };

    // ldmatrix lane addressing components
    const int aRow = lane & 15;          // A: row within m16 tile
    const int aSel = lane >> 4;          // A: which k-chunk (0/1)
    const int bRow = (lane & 7) + ((lane >> 4) << 3);  // B: n row within 16
    const int bSel = (lane >> 3) & 1;    // B: which k-chunk

    auto compute_chunk = [&](uint32_t stbase) {
#pragma unroll
        for (int ks = 0; ks < 2; ks++) {
            const int kc = ks * 2;
            uint32_t aH[4][4], aL[4][4], bH[2][4], bL[2][4];
#pragma unroll
            for (int mf = 0; mf < 4; mf++) {
                uint32_t o = sw_off(wm0 + mf * 16 + aRow, kc + aSel);
                ldsm4(aH[mf], stbase + AH_OFF + o);
                ldsm4(aL[mf], stbase + AL_OFF + o);
            }
#pragma unroll
            for (int p = 0; p < 2; p++) {
                uint32_t o = sw_off(wn0 + p * 16 + bRow, kc + bSel);
                ldsm4(bH[p], stbase + BH_OFF + o);
                ldsm4(bL[p], stbase + BL_OFF + o);
            }
#pragma unroll
            for (int mf = 0; mf < 4; mf++) {
#pragma unroll
                for (int nf = 0; nf < 4; nf++) {
                    const uint32_t* bh = &bH[nf >> 1][(nf & 1) * 2];
                    const uint32_t* bl = &bL[nf >> 1][(nf & 1) * 2];
                    mma16816(acc[mf][nf], aH[mf], bh);   // hi*hi
                    mma16816(acc[mf][nf], aH[mf], bl);   // hi*lo
                    mma16816(acc[mf][nf], aL[mf], bh);   // lo*hi
                }
            }
        }
    };

    // ---- pipelined mainloop ----
    load_chunk(0);
    for (int c = 0; c < nk; c++) {
        char* st = smem + (c & 1) * STAGE_BYTES;
        store_chunk(st);
        __syncthreads();
        if (c + 1 < nk) load_chunk(c + 1);
        compute_chunk(sb + (uint32_t)((c & 1) * STAGE_BYTES));
    }

    // ---- epilogue ----
    const int g = lane >> 2, t = lane & 3;

    if (MODE == MODE_MEN) {
#pragma unroll
        for (int mf = 0; mf < 4; mf++) {
            float s0 = 0.0f, s1 = 0.0f;
#pragma unroll
            for (int nf = 0; nf < 4; nf++) {
#pragma unroll
                for (int q = 0; q < 2; q++) {
                    int n = n0 + wn0 + nf * 8 + 2 * t + q;
                    float w = (n < N) ? wo[n] : 0.0f;
                    s0 += ftanh(acc[mf][nf][q])     * w;
                    s1 += ftanh(acc[mf][nf][2 + q]) * w;
                }
            }
            s0 += __shfl_xor_sync(0xffffffffu, s0, 1);
            s0 += __shfl_xor_sync(0xffffffffu, s0, 2);
            s1 += __shfl_xor_sync(0xffffffffu, s1, 1);
            s1 += __shfl_xor_sync(0xffffffffu, s1, 2);
            if (t == 0) {
                int m = m0 + wm0 + mf * 16 + g;
                if (m < M)     atomicAdd(&rowAcc[m], s0);
                if (m + 8 < M) atomicAdd(&rowAcc[m + 8], s1);
            }
        }
    } else {
        float ls = (MODE == MODE_OUT) ? *scal : 0.0f;
#pragma unroll
        for (int mf = 0; mf < 4; mf++) {
            int mA = m0 + wm0 + mf * 16 + g;
            int mB = mA + 8;
#pragma unroll
            for (int nf = 0; nf < 4; nf++) {
                int n = n0 + wn0 + nf * 8 + 2 * t;
#pragma unroll
                for (int q = 0; q < 2; q++) {
                    int nn = n + q;
                    if (nn < N) {
                        if (mA < M) {
                            size_t idx = (size_t)mA * ldc + nn;
                            float v = acc[mf][nf][q];
                            if (MODE == MODE_OUT) v += ls * aux[idx];
                            C[idx] = v;
                        }
                        if (mB < M) {
                            size_t idx = (size_t)mB * ldc + nn;
                            float v = acc[mf][nf][2 + q];
                            if (MODE == MODE_OUT) v += ls * aux[idx];
                            C[idx] = v;
                        }
                    }
                }
            }
        }
    }
}

// ---------------- masked softmax over S + weighted sum over x ----------------
__global__ void attn_kernel(const float* __restrict__ elmo,
                            const int* __restrict__ gathers,
                            const float* __restrict__ scores,
                            const float* __restrict__ mask,
                            int gatherScores,
                            float* __restrict__ outBase)
{
    int b = blockIdx.x;
    int tid = threadIdx.x;
    __shared__ float attn_s[SEQ];
    __shared__ float red[8];
    int g = gathers[b];

    float sc = -1e30f;
    if (tid < SEQ) {
        float raw = gatherScores ? scores[g * SEQ + tid] : scores[b * SEQ + tid];
        sc = raw + (1.0f - mask[b * SEQ + tid]) * NEGV;
    }
    float v = sc;
#pragma unroll
    for (int off = 16; off > 0; off >>= 1)
        v = fmaxf(v, __shfl_xor_sync(0xffffffffu, v, off));
    if ((tid & 31) == 0) red[tid >> 5] = v;
    __syncthreads();
    float mx = fmaxf(fmaxf(red[0], red[1]), fmaxf(red[2], red[3]));
    __syncthreads();

    float e = (tid < SEQ) ? __expf(sc - mx) : 0.0f;
    v = e;
#pragma unroll
    for (int off = 16; off > 0; off >>= 1)
        v += __shfl_xor_sync(0xffffffffu, v, off);
    if ((tid & 31) == 0) red[tid >> 5] = v;
    __syncthreads();
    float sum = red[0] + red[1] + red[2] + red[3];
    if (tid < SEQ) attn_s[tid] = e / sum;
    __syncthreads();

    const float4* xr = reinterpret_cast<const float4*>(elmo + (size_t)g * SEQ * DIM);
    float4 accv = make_float4(0.f, 0.f, 0.f, 0.f);
#pragma unroll 4
    for (int s = 0; s < SEQ; s++) {
        float a = attn_s[s];
        float4 x = xr[(size_t)s * (DIM / 4) + tid];
        accv.x = fmaf(a, x.x, accv.x);
        accv.y = fmaf(a, x.y, accv.y);
        accv.z = fmaf(a, x.z, accv.z);
        accv.w = fmaf(a, x.w, accv.w);
    }
    reinterpret_cast<float4*>(outBase + (size_t)b * DIM2)[tid] = accv;
}

// ---------------- fused context score (warp-per-s) ---------------------------
__global__ void ctx_score_kernel(const int* __restrict__ gathers,
                                 const float* __restrict__ dist,
                                 const float* __restrict__ wd,
                                 const float* __restrict__ wo)
{
    int b = blockIdx.x;
    int tid = threadIdx.x;   // 256 threads = 8 warps
    int w = tid >> 5, lid = tid & 31;
    __shared__ __align__(16) float s_m2[DIM];
    __shared__ __align__(16) float s_wd[DIM];
    __shared__ __align__(16) float s_wo[DIM];
    int g = gathers[b];
    for (int i = tid; i < DIM; i += 256) {
        s_m2[i] = g_m2[(size_t)b * DIM + i];
        s_wd[i] = wd[i];
        s_wo[i] = wo[i];
    }
    __syncthreads();

    const float4* c1 = reinterpret_cast<const float4*>(g_C1) + (size_t)g * SEQ * (DIM / 4);
    const float4* m2v = reinterpret_cast<const float4*>(s_m2);
    const float4* wdv = reinterpret_cast<const float4*>(s_wd);
    const float4* wov = reinterpret_cast<const float4*>(s_wo);

    for (int s = w; s < SEQ; s += 8) {
        float dv = dist[b * SEQ + s];
        float p = 0.0f;
#pragma unroll
        for (int j0 = 0; j0 < 8; j0++) {
            int j = lid + j0 * 32;
            float4 c = c1[(size_t)s * (DIM / 4) + j];
            float4 m = m2v[j], d = wdv[j], o = wov[j];
            p += o.x * ftanh(c.x + m.x + dv * d.x)
               + o.y * ftanh(c.y + m.y + dv * d.y)
               + o.z * ftanh(c.z + m.z + dv * d.z)
               + o.w * ftanh(c.w + m.w + dv * d.w);
        }
#pragma unroll
        for (int off = 16; off > 0; off >>= 1)
            p += __shfl_xor_sync(0xffffffffu, p, off);
        if (lid == 0) g_ctxScore[b * SEQ + s] = p;
    }
}

// ---------------- latent = final @ W_f2l^T  [B, 101] --------------------------
__global__ void latent_kernel(const float* __restrict__ Wf2l)
{
    int b = blockIdx.x;
    int tid = threadIdx.x;   // 128 threads
    __shared__ __align__(16) float4 sf[DIM2 / 4];
    const float4* fr = reinterpret_cast<const float4*>(&g_final[(size_t)b * DIM2]);
    for (int i = tid; i < DIM2 / 4; i += 128) sf[i] = fr[i];
    __syncthreads();
    if (tid < LATD) {
        const float4* wr = reinterpret_cast<const float4*>(Wf2l + (size_t)tid * DIM2);
        float acc = 0.0f;
#pragma unroll 4
        for (int k = 0; k < DIM2 / 4; k++) {
            float4 wv = wr[k];
            float4 f = sf[k];
            acc += wv.x * f.x + wv.y * f.y + wv.z * f.z + wv.w * f.w;
        }
        g_latent[b * LATD + tid] = acc;
    }
}

// ---------------- launch ------------------------------------------------------
extern "C" void kernel_launch(void* const* d_in, const int* in_sizes, int n_in,
                              void* d_out, int out_size)
{
    const float* elmo     = (const float*)d_in[0];
    const float* men_mask = (const float*)d_in[1];
    const float* ctx_mask = (const float*)d_in[2];
    const float* dist     = (const float*)d_in[3];
    const int*   gathers  = (const int*)  d_in[4];
    const float* W_men_m  = (const float*)d_in[5];
    const float* W_men_o  = (const float*)d_in[6];
    const float* W_ctx_c  = (const float*)d_in[7];
    const float* W_ctx_m  = (const float*)d_in[8];
    const float* w_ctx_d  = (const float*)d_in[9];
    const float* W_ctx_o  = (const float*)d_in[10];
    const float* W_out    = (const float*)d_in[11];
    const float* W_f2l    = (const float*)d_in[12];
    const float* W_l2l    = (const float*)d_in[13];
    const float* lscal    = (const float*)d_in[14];

    float* out_main = (float*)d_out;
    float* out_lat  = out_main + (size_t)BATCH * LBL;

    float *pC1, *pMS, *pCS, *pFin, *pM2, *pLat;
    cudaGetSymbolAddress((void**)&pC1,  g_C1);
    cudaGetSymbolAddress((void**)&pMS,  g_menScore);
    cudaGetSymbolAddress((void**)&pCS,  g_ctxScore);
    cudaGetSymbolAddress((void**)&pFin, g_final);
    cudaGetSymbolAddress((void**)&pM2,  g_m2);
    cudaGetSymbolAddress((void**)&pLat, g_latent);

    cudaFuncSetAttribute(gemm_mma<MODE_STORE>, cudaFuncAttributeMaxDynamicSharedMemorySize, SMEM_GEMM);
    cudaFuncSetAttribute(gemm_mma<MODE_MEN>,   cudaFuncAttributeMaxDynamicSharedMemorySize, SMEM_GEMM);
    cudaFuncSetAttribute(gemm_mma<MODE_OUT>,   cudaFuncAttributeMaxDynamicSharedMemorySize, SMEM_GEMM);

    // 1. zero mention-score accumulator
    zero_kernel<<<(N_SENTC * SEQ + 255) / 256, 256>>>(pMS, N_SENTC * SEQ);

    // 2. per-sentence mention scores (fused tanh*wo epilogue): M=32768 N=1024 K=1024
    gemm_mma<MODE_MEN><<<dim3(8, 256), 256, SMEM_GEMM>>>(
        elmo, DIM, W_men_m, DIM, nullptr, 0,
        N_SENTC * SEQ, DIM, DIM, W_men_o, pMS, nullptr, nullptr);

    // 3. C1 = elmo @ W_ctx_c^T
    gemm_mma<MODE_STORE><<<dim3(8, 256), 256, SMEM_GEMM>>>(
        elmo, DIM, W_ctx_c, DIM, pC1, DIM,
        N_SENTC * SEQ, DIM, DIM, nullptr, nullptr, nullptr, nullptr);

    // 4. mention softmax + men_repr -> final[:, 0:1024]
    attn_kernel<<<BATCH, 256>>>(elmo, gathers, pMS, men_mask, 1, pFin);

    // 5. m2 = men_repr @ W_ctx_m^T (M=512, N=1024, K=1024; lda=2048)
    gemm_mma<MODE_STORE><<<dim3(8, 4), 256, SMEM_GEMM>>>(
        pFin, DIM2, W_ctx_m, DIM, pM2, DIM,
        BATCH, DIM, DIM, nullptr, nullptr, nullptr, nullptr);

    // 6. fused context scores
    ctx_score_kernel<<<BATCH, 256>>>(gathers, dist, w_ctx_d, W_ctx_o);

    // 7. context softmax + ctx_repr -> final[:, 1024:2048]
    attn_kernel<<<BATCH, 256>>>(elmo, gathers, pCS, ctx_mask, 0, pFin + DIM);

    // 8. latent = final @ W_f2l^T  [512, 101]
    latent_kernel<<<BATCH, 128>>>(W_f2l);

    // 9. outputs_latent = latent @ W_l2l^T (M=512, N=10331, K=101)
    gemm_mma<MODE_STORE><<<dim3(81, 4), 256, SMEM_GEMM>>>(
        pLat, LATD, W_l2l, LATD, out_lat, LBL,
        BATCH, LBL, LATD, nullptr, nullptr, nullptr, nullptr);

    // 10. outputs = final @ W_out^T + latent_scalar * outputs_latent
    gemm_mma<MODE_OUT><<<dim3(81, 4), 256, SMEM_GEMM>>>(
        pFin, DIM2, W_out, DIM2, out_main, LBL,
        BATCH, LBL, DIM2, nullptr, nullptr, out_lat, lscal);
}

// round 8
// speedup vs baseline: 2.7996x; 1.4416x over previous
#include <cuda_runtime.h>
#include <cuda_bf16.h>
#include <cstdint>
#include <math.h>

#define N_SENTC 256
#define BATCH   512
#define SEQ     128
#define DIM     1024
#define LBL     10331
#define LATD    101
#define LATP    128          // padded K for latent GEMM
#define DIM2    2048
#define NEGV    (-10000.0f)

// ---------------- scratch -----------------------------------------------------
__device__ float g_C1[(size_t)N_SENTC * SEQ * DIM];
__device__ float g_menScore[N_SENTC * SEQ];
__device__ float g_ctxScore[BATCH * SEQ];
__device__ float g_final[BATCH * DIM2];
__device__ float g_m2[BATCH * DIM];

// bf16 hi/lo operand scratch
__device__ __nv_bfloat16 g_eH[(size_t)N_SENTC * SEQ * DIM];
__device__ __nv_bfloat16 g_eL[(size_t)N_SENTC * SEQ * DIM];
__device__ __nv_bfloat16 g_WmH[DIM * DIM],  g_WmL[DIM * DIM];
__device__ __nv_bfloat16 g_WcH[DIM * DIM],  g_WcL[DIM * DIM];
__device__ __nv_bfloat16 g_WcmH[DIM * DIM], g_WcmL[DIM * DIM];
__device__ __nv_bfloat16 g_WoH[(size_t)LBL * DIM2], g_WoL[(size_t)LBL * DIM2];
__device__ __nv_bfloat16 g_Wl2lH[(size_t)LBL * LATP], g_Wl2lL[(size_t)LBL * LATP];
__device__ __nv_bfloat16 g_fH[BATCH * DIM2], g_fL[BATCH * DIM2];
__device__ __nv_bfloat16 g_latH[BATCH * LATP], g_latL[BATCH * LATP];

// ---------------- helpers -----------------------------------------------------
__device__ __forceinline__ uint32_t smem_to_u32(const void* p) {
    uint32_t a;
    asm("{ .reg .u64 t; cvta.to.shared.u64 t, %1; cvt.u32.u64 %0, t; }" : "=r"(a) : "l"(p));
    return a;
}
__device__ __forceinline__ float ftanh(float x) {
    float e = __expf(2.0f * x);
    return 1.0f - __fdividef(2.0f, e + 1.0f);
}
__device__ __forceinline__ void split1(float x, __nv_bfloat16& h, __nv_bfloat16& l) {
    h = __float2bfloat16(x);
    l = __float2bfloat16(x - __bfloat162float(h));
}
__device__ __forceinline__ void split4(float4 v, uint2& hi, uint2& lo) {
    __nv_bfloat16 h[4], l[4];
    split1(v.x, h[0], l[0]); split1(v.y, h[1], l[1]);
    split1(v.z, h[2], l[2]); split1(v.w, h[3], l[3]);
    hi.x = (uint32_t)__bfloat16_as_ushort(h[0]) | ((uint32_t)__bfloat16_as_ushort(h[1]) << 16);
    hi.y = (uint32_t)__bfloat16_as_ushort(h[2]) | ((uint32_t)__bfloat16_as_ushort(h[3]) << 16);
    lo.x = (uint32_t)__bfloat16_as_ushort(l[0]) | ((uint32_t)__bfloat16_as_ushort(l[1]) << 16);
    lo.y = (uint32_t)__bfloat16_as_ushort(l[2]) | ((uint32_t)__bfloat16_as_ushort(l[3]) << 16);
}

__global__ void zero_kernel(float* p, int n) {
    int i = blockIdx.x * blockDim.x + threadIdx.x;
    if (i < n) p[i] = 0.0f;
}

// fp32 -> bf16 hi/lo (n4 = n/4 float4 groups)
__global__ void cvt_hilo(const float* __restrict__ src, __nv_bfloat16* __restrict__ h,
                         __nv_bfloat16* __restrict__ l, int n4) {
    int i = blockIdx.x * blockDim.x + threadIdx.x;
    if (i < n4) {
        float4 v = reinterpret_cast<const float4*>(src)[i];
        uint2 hi, lo; split4(v, hi, lo);
        reinterpret_cast<uint2*>(h)[i] = hi;
        reinterpret_cast<uint2*>(l)[i] = lo;
    }
}

// W_l2l [LBL,101] fp32 -> [LBL,128] bf16 hi/lo (zero-padded)
__global__ void cvt_l2l(const float* __restrict__ src,
                        __nv_bfloat16* __restrict__ h, __nv_bfloat16* __restrict__ l) {
    int i = blockIdx.x * blockDim.x + threadIdx.x;
    if (i < LBL * LATP) {
        int r = i >> 7, c = i & 127;
        float v = (c < LATD) ? src[r * LATD + c] : 0.0f;
        __nv_bfloat16 hh, ll; split1(v, hh, ll);
        h[i] = hh; l[i] = ll;
    }
}

// ---------------- warp-mma + cp.async primitives ------------------------------
__device__ __forceinline__ void ldsm4(uint32_t* r, uint32_t addr) {
    asm volatile("ldmatrix.sync.aligned.m8n8.x4.shared.b16 {%0,%1,%2,%3}, [%4];"
                 : "=r"(r[0]), "=r"(r[1]), "=r"(r[2]), "=r"(r[3]) : "r"(addr));
}
__device__ __forceinline__ void mma16816(float (&c)[4], const uint32_t* a, const uint32_t* b) {
    asm volatile("mma.sync.aligned.m16n8k16.row.col.f32.bf16.bf16.f32 "
                 "{%0,%1,%2,%3}, {%4,%5,%6,%7}, {%8,%9}, {%0,%1,%2,%3};"
                 : "+f"(c[0]), "+f"(c[1]), "+f"(c[2]), "+f"(c[3])
                 : "r"(a[0]), "r"(a[1]), "r"(a[2]), "r"(a[3]), "r"(b[0]), "r"(b[1]));
}
__device__ __forceinline__ void cp16(uint32_t saddr, const void* gaddr, int src_size) {
    asm volatile("cp.async.cg.shared.global [%0], [%1], 16, %2;"
                 :: "r"(saddr), "l"(gaddr), "r"(src_size) : "memory");
}
#define CP_COMMIT() asm volatile("cp.async.commit_group;" ::: "memory")
#define CP_WAIT1()  asm volatile("cp.async.wait_group 1;" ::: "memory")
#define CP_WAIT0()  asm volatile("cp.async.wait_group 0;" ::: "memory")

// stage: 128 rows x 64 bf16 (128B rows, 8 chunks of 16B, XOR-8 swizzle) x4 tiles
#define STAGES 3
#define AH_OFF 0
#define AL_OFF 16384
#define BH_OFF 32768
#define BL_OFF 49152
#define STAGE_BYTES 65536
#define SMEM_GEMM (STAGES * STAGE_BYTES)

// ---------------- shared GEMM core: acc += A*B^T over K (bf16 hi/lo, 3-pass) --
// A:[*,lda] hi/lo, B:[N,ldb] hi/lo. CTA tile 128x128, BK=64, 256 thr (8 warps).
// Requires: M a multiple of 128 (no A row guard), K a multiple of 64, lda/ldb even.
__device__ __forceinline__ void gemm_core(
    const __nv_bfloat16* __restrict__ AH_, const __nv_bfloat16* __restrict__ AL_, int lda,
    const __nv_bfloat16* __restrict__ BH_, const __nv_bfloat16* __restrict__ BL_, int ldb,
    int N, int K, int m0, int n0, char* smem, float (&acc)[4][4][4])
{
    const uint32_t sb = smem_to_u32(smem);
    const int tid  = threadIdx.x;
    const int lane = tid & 31;
    const int wid  = tid >> 5;
    const int wm0  = (wid >> 2) * 64;
    const int wn0  = (wid & 3) * 32;
    const int nk   = K >> 6;

#pragma unroll
    for (int i = 0; i < 4; i++)
#pragma unroll
        for (int j = 0; j < 4; j++)
#pragma unroll
            for (int q = 0; q < 4; q++) acc[i][j][q] = 0.0f;

    const int aRow = lane & 15, aSel = lane >> 4;
    const int bRow = (lane & 7) + ((lane >> 4) << 3);
    const int bSel = (lane >> 3) & 1;
    const int crow = tid >> 3;          // copy row base (0..31)
    const int cch  = tid & 7;           // copy 16B chunk

    auto issue = [&](int c) {
        if (c >= nk) return;
        const int kb = c * 64;
        uint32_t stb = sb + (c % STAGES) * STAGE_BYTES;
#pragma unroll
        for (int q = 0; q < 4; q++) {
            int row = crow + q * 32;
            uint32_t so = (uint32_t)(row * 128 + (((cch ^ (row & 7)) & 7) << 4));
            size_t ga = (size_t)(m0 + row) * lda + kb + cch * 8;
            cp16(stb + AH_OFF + so, AH_ + ga, 16);
            cp16(stb + AL_OFF + so, AL_ + ga, 16);
            int br = n0 + row;
            int ok = (br < N) ? 16 : 0;
            size_t gb = (size_t)min(br, N - 1) * ldb + kb + cch * 8;
            cp16(stb + BH_OFF + so, BH_ + gb, ok);
            cp16(stb + BL_OFF + so, BL_ + gb, ok);
        }
    };

    issue(0); CP_COMMIT();
    issue(1); CP_COMMIT();

    for (int c = 0; c < nk; c++) {
        if (c + STAGES - 1 < nk) { CP_WAIT1(); } else { CP_WAIT0(); }
        __syncthreads();
        issue(c + STAGES - 1); CP_COMMIT();
        uint32_t stb = sb + (c % STAGES) * STAGE_BYTES;
#pragma unroll
        for (int ks = 0; ks < 4; ks++) {
            const int kc = ks * 2;
            uint32_t aH[4][4], aL[4][4], bH[2][4], bL[2][4];
#pragma unroll
            for (int mf = 0; mf < 4; mf++) {
                int r = wm0 + mf * 16 + aRow;
                int ch = kc + aSel;
                uint32_t o = (uint32_t)(r * 128 + (((ch ^ (r & 7)) & 7) << 4));
                ldsm4(aH[mf], stb + AH_OFF + o);
                ldsm4(aL[mf], stb + AL_OFF + o);
            }
#pragma unroll
            for (int p = 0; p < 2; p++) {
                int r = wn0 + p * 16 + bRow;
                int ch = kc + bSel;
                uint32_t o = (uint32_t)(r * 128 + (((ch ^ (r & 7)) & 7) << 4));
                ldsm4(bH[p], stb + BH_OFF + o);
                ldsm4(bL[p], stb + BL_OFF + o);
            }
#pragma unroll
            for (int mf = 0; mf < 4; mf++) {
#pragma unroll
                for (int nf = 0; nf < 4; nf++) {
                    const uint32_t* bh = &bH[nf >> 1][(nf & 1) * 2];
                    const uint32_t* bl = &bL[nf >> 1][(nf & 1) * 2];
                    mma16816(acc[mf][nf], aH[mf], bh);
                    mma16816(acc[mf][nf], aL[mf], bh);
                    mma16816(acc[mf][nf], aH[mf], bl);
                }
            }
        }
    }
}

// ---------------- fused big kernel: mention scores + C1 -----------------------
// grid (16, 256): x<8 -> B=W_men_m, tanh*wo row-reduce; x>=8 -> B=W_ctx_c, store C1
__global__ __launch_bounds__(256, 1)
void gemm_big(const __nv_bfloat16* __restrict__ eH, const __nv_bfloat16* __restrict__ eL,
              const __nv_bfloat16* __restrict__ wmH, const __nv_bfloat16* __restrict__ wmL,
              const __nv_bfloat16* __restrict__ wcH, const __nv_bfloat16* __restrict__ wcL,
              const float* __restrict__ wo, float* __restrict__ rowAcc,
              float* __restrict__ C1)
{
    extern __shared__ char smem[];
    const bool isMen = blockIdx.x < 8;
    const int n0 = (blockIdx.x & 7) * 128;
    const int m0 = blockIdx.y * 128;
    const int lane = threadIdx.x & 31;
    const int wid  = threadIdx.x >> 5;
    const int wm0  = (wid >> 2) * 64;
    const int wn0  = (wid & 3) * 32;

    float acc[4][4][4];
    gemm_core(eH, eL, DIM, isMen ? wmH : wcH, isMen ? wmL : wcL, DIM,
              DIM, DIM, m0, n0, smem, acc);

    const int g = lane >> 2, t = lane & 3;
    if (isMen) {
#pragma unroll
        for (int mf = 0; mf < 4; mf++) {
            float s0 = 0.0f, s1 = 0.0f;
#pragma unroll
            for (int nf = 0; nf < 4; nf++) {
#pragma unroll
                for (int q = 0; q < 2; q++) {
                    int n = n0 + wn0 + nf * 8 + 2 * t + q;
                    float w = wo[n];
                    s0 += ftanh(acc[mf][nf][q])     * w;
                    s1 += ftanh(acc[mf][nf][2 + q]) * w;
                }
            }
            s0 += __shfl_xor_sync(0xffffffffu, s0, 1);
            s0 += __shfl_xor_sync(0xffffffffu, s0, 2);
            s1 += __shfl_xor_sync(0xffffffffu, s1, 1);
            s1 += __shfl_xor_sync(0xffffffffu, s1, 2);
            if (t == 0) {
                int m = m0 + wm0 + mf * 16 + g;
                atomicAdd(&rowAcc[m], s0);
                atomicAdd(&rowAcc[m + 8], s1);
            }
        }
    } else {
#pragma unroll
        for (int mf = 0; mf < 4; mf++) {
            int mA = m0 + wm0 + mf * 16 + g;
#pragma unroll
            for (int nf = 0; nf < 4; nf++) {
                int n = n0 + wn0 + nf * 8 + 2 * t;
                size_t iA = (size_t)mA * DIM + n;
                size_t iB = (size_t)(mA + 8) * DIM + n;
                C1[iA]     = acc[mf][nf][0];
                C1[iA + 1] = acc[mf][nf][1];
                C1[iB]     = acc[mf][nf][2];
                C1[iB + 1] = acc[mf][nf][3];
            }
        }
    }
}

// ---------------- generic GEMM kernel (STORE / OUT epilogues) -----------------
enum { MODE_STORE = 0, MODE_OUT = 2 };

template <int MODE>
__global__ __launch_bounds__(256, 1)
void gemm_bf(const __nv_bfloat16* __restrict__ AH_, const __nv_bfloat16* __restrict__ AL_, int lda,
             const __nv_bfloat16* __restrict__ BH_, const __nv_bfloat16* __restrict__ BL_, int ldb,
             float* __restrict__ C, int ldc, int N, int K,
             const float* __restrict__ aux, const float* __restrict__ scal)
{
    extern __shared__ char smem[];
    const int n0 = blockIdx.x * 128;
    const int m0 = blockIdx.y * 128;
    const int lane = threadIdx.x & 31;
    const int wid  = threadIdx.x >> 5;
    const int wm0  = (wid >> 2) * 64;
    const int wn0  = (wid & 3) * 32;

    float acc[4][4][4];
    gemm_core(AH_, AL_, lda, BH_, BL_, ldb, N, K, m0, n0, smem, acc);

    const int g = lane >> 2, t = lane & 3;
    const float ls = (MODE == MODE_OUT) ? *scal : 0.0f;
#pragma unroll
    for (int mf = 0; mf < 4; mf++) {
        int mA = m0 + wm0 + mf * 16 + g;
#pragma unroll
        for (int nf = 0; nf < 4; nf++) {
            int n = n0 + wn0 + nf * 8 + 2 * t;
#pragma unroll
            for (int q = 0; q < 2; q++) {
                int nn = n + q;
                if (nn < N) {
                    size_t iA = (size_t)mA * ldc + nn;
                    size_t iB = (size_t)(mA + 8) * ldc + nn;
                    float v0 = acc[mf][nf][q];
                    float v1 = acc[mf][nf][2 + q];
                    if (MODE == MODE_OUT) { v0 += ls * aux[iA]; v1 += ls * aux[iB]; }
                    C[iA] = v0;
                    C[iB] = v1;
                }
            }
        }
    }
}

// ---------------- masked softmax over S + weighted sum ------------------------
__global__ void attn_kernel(const float* __restrict__ elmo,
                            const int* __restrict__ gathers,
                            const float* __restrict__ scores,
                            const float* __restrict__ mask,
                            int gatherScores,
                            float* __restrict__ outBase,
                            __nv_bfloat16* __restrict__ outH,
                            __nv_bfloat16* __restrict__ outL)
{
    int b = blockIdx.x;
    int tid = threadIdx.x;
    __shared__ float attn_s[SEQ];
    __shared__ float red[8];
    int g = gathers[b];

    float sc = -1e30f;
    if (tid < SEQ) {
        float raw = gatherScores ? scores[g * SEQ + tid] : scores[b * SEQ + tid];
        sc = raw + (1.0f - mask[b * SEQ + tid]) * NEGV;
    }
    float v = sc;
#pragma unroll
    for (int off = 16; off > 0; off >>= 1)
        v = fmaxf(v, __shfl_xor_sync(0xffffffffu, v, off));
    if ((tid & 31) == 0) red[tid >> 5] = v;
    __syncthreads();
    float mx = fmaxf(fmaxf(red[0], red[1]), fmaxf(red[2], red[3]));
    __syncthreads();

    float e = (tid < SEQ) ? __expf(sc - mx) : 0.0f;
    v = e;
#pragma unroll
    for (int off = 16; off > 0; off >>= 1)
        v += __shfl_xor_sync(0xffffffffu, v, off);
    if ((tid & 31) == 0) red[tid >> 5] = v;
    __syncthreads();
    float sum = red[0] + red[1] + red[2] + red[3];
    if (tid < SEQ) attn_s[tid] = e / sum;
    __syncthreads();

    const float4* xr = reinterpret_cast<const float4*>(elmo + (size_t)g * SEQ * DIM);
    float4 accv = make_float4(0.f, 0.f, 0.f, 0.f);
#pragma unroll 4
    for (int s = 0; s < SEQ; s++) {
        float a = attn_s[s];
        float4 x = xr[(size_t)s * (DIM / 4) + tid];
        accv.x = fmaf(a, x.x, accv.x);
        accv.y = fmaf(a, x.y, accv.y);
        accv.z = fmaf(a, x.z, accv.z);
        accv.w = fmaf(a, x.w, accv.w);
    }
    size_t idx = (size_t)b * DIM2 + 4 * tid;
    *reinterpret_cast<float4*>(outBase + idx) = accv;
    uint2 hi, lo; split4(accv, hi, lo);
    *reinterpret_cast<uint2*>(outH + idx) = hi;
    *reinterpret_cast<uint2*>(outL + idx) = lo;
}

// ---------------- fused context score (warp-per-s) ----------------------------
__global__ void ctx_score_kernel(const int* __restrict__ gathers,
                                 const float* __restrict__ dist,
                                 const float* __restrict__ wd,
                                 const float* __restrict__ wo)
{
    int b = blockIdx.x;
    int tid = threadIdx.x;
    int w = tid >> 5, lid = tid & 31;
    __shared__ __align__(16) float s_m2[DIM];
    __shared__ __align__(16) float s_wd[DIM];
    __shared__ __align__(16) float s_wo[DIM];
    int g = gathers[b];
    for (int i = tid; i < DIM; i += 256) {
        s_m2[i] = g_m2[(size_t)b * DIM + i];
        s_wd[i] = wd[i];
        s_wo[i] = wo[i];
    }
    __syncthreads();

    const float4* c1 = reinterpret_cast<const float4*>(g_C1) + (size_t)g * SEQ * (DIM / 4);
    const float4* m2v = reinterpret_cast<const float4*>(s_m2);
    const float4* wdv = reinterpret_cast<const float4*>(s_wd);
    const float4* wov = reinterpret_cast<const float4*>(s_wo);

    for (int s = w; s < SEQ; s += 8) {
        float dv = dist[b * SEQ + s];
        float p = 0.0f;
#pragma unroll
        for (int j0 = 0; j0 < 8; j0++) {
            int j = lid + j0 * 32;
            float4 c = c1[(size_t)s * (DIM / 4) + j];
            float4 m = m2v[j], d = wdv[j], o = wov[j];
            p += o.x * ftanh(c.x + m.x + dv * d.x)
               + o.y * ftanh(c.y + m.y + dv * d.y)
               + o.z * ftanh(c.z + m.z + dv * d.z)
               + o.w * ftanh(c.w + m.w + dv * d.w);
        }
#pragma unroll
        for (int off = 16; off > 0; off >>= 1)
            p += __shfl_xor_sync(0xffffffffu, p, off);
        if (lid == 0) g_ctxScore[b * SEQ + s] = p;
    }
}

// ---------------- latent = final @ W_f2l^T -> bf16 hi/lo padded ---------------
__global__ void latent_kernel(const float* __restrict__ Wf2l)
{
    int b = blockIdx.x;
    int tid = threadIdx.x;   // 128 threads
    __shared__ __align__(16) float4 sf[DIM2 / 4];
    const float4* fr = reinterpret_cast<const float4*>(&g_final[(size_t)b * DIM2]);
    for (int i = tid; i < DIM2 / 4; i += 128) sf[i] = fr[i];
    __syncthreads();
    float acc = 0.0f;
    if (tid < LATD) {
        const float4* wr = reinterpret_cast<const float4*>(Wf2l + (size_t)tid * DIM2);
#pragma unroll 4
        for (int k = 0; k < DIM2 / 4; k++) {
            float4 wv = wr[k];
            float4 f = sf[k];
            acc += wv.x * f.x + wv.y * f.y + wv.z * f.z + wv.w * f.w;
        }
    }
    __nv_bfloat16 h, l; split1(tid < LATD ? acc : 0.0f, h, l);
    g_latH[b * LATP + tid] = h;
    g_latL[b * LATP + tid] = l;
}

// ---------------- launch ------------------------------------------------------
extern "C" void kernel_launch(void* const* d_in, const int* in_sizes, int n_in,
                              void* d_out, int out_size)
{
    const float* elmo     = (const float*)d_in[0];
    const float* men_mask = (const float*)d_in[1];
    const float* ctx_mask = (const float*)d_in[2];
    const float* dist     = (const float*)d_in[3];
    const int*   gathers  = (const int*)  d_in[4];
    const float* W_men_m  = (const float*)d_in[5];
    const float* W_men_o  = (const float*)d_in[6];
    const float* W_ctx_c  = (const float*)d_in[7];
    const float* W_ctx_m  = (const float*)d_in[8];
    const float* w_ctx_d  = (const float*)d_in[9];
    const float* W_ctx_o  = (const float*)d_in[10];
    const float* W_out    = (const float*)d_in[11];
    const float* W_f2l    = (const float*)d_in[12];
    const float* W_l2l    = (const float*)d_in[13];
    const float* lscal    = (const float*)d_in[14];

    float* out_main = (float*)d_out;
    float* out_lat  = out_main + (size_t)BATCH * LBL;

    float *pC1, *pMS, *pCS, *pFin, *pM2;
    cudaGetSymbolAddress((void**)&pC1,  g_C1);
    cudaGetSymbolAddress((void**)&pMS,  g_menScore);
    cudaGetSymbolAddress((void**)&pCS,  g_ctxScore);
    cudaGetSymbolAddress((void**)&pFin, g_final);
    cudaGetSymbolAddress((void**)&pM2,  g_m2);
    __nv_bfloat16 *pEH, *pEL, *pWmH, *pWmL, *pWcH, *pWcL, *pWcmH, *pWcmL;
    __nv_bfloat16 *pWoH, *pWoL, *pl2lH, *pl2lL, *pFH, *pFL, *pLaH, *pLaL;
    cudaGetSymbolAddress((void**)&pEH,   g_eH);
    cudaGetSymbolAddress((void**)&pEL,   g_eL);
    cudaGetSymbolAddress((void**)&pWmH,  g_WmH);
    cudaGetSymbolAddress((void**)&pWmL,  g_WmL);
    cudaGetSymbolAddress((void**)&pWcH,  g_WcH);
    cudaGetSymbolAddress((void**)&pWcL,  g_WcL);
    cudaGetSymbolAddress((void**)&pWcmH, g_WcmH);
    cudaGetSymbolAddress((void**)&pWcmL, g_WcmL);
    cudaGetSymbolAddress((void**)&pWoH,  g_WoH);
    cudaGetSymbolAddress((void**)&pWoL,  g_WoL);
    cudaGetSymbolAddress((void**)&pl2lH, g_Wl2lH);
    cudaGetSymbolAddress((void**)&pl2lL, g_Wl2lL);
    cudaGetSymbolAddress((void**)&pFH,   g_fH);
    cudaGetSymbolAddress((void**)&pFL,   g_fL);
    cudaGetSymbolAddress((void**)&pLaH,  g_latH);
    cudaGetSymbolAddress((void**)&pLaL,  g_latL);

    cudaFuncSetAttribute(gemm_big,            cudaFuncAttributeMaxDynamicSharedMemorySize, SMEM_GEMM);
    cudaFuncSetAttribute(gemm_bf<MODE_STORE>, cudaFuncAttributeMaxDynamicSharedMemorySize, SMEM_GEMM);
    cudaFuncSetAttribute(gemm_bf<MODE_OUT>,   cudaFuncAttributeMaxDynamicSharedMemorySize, SMEM_GEMM);

    // ---- operand conversions (fp32 -> bf16 hi/lo) ----
    {
        int n4 = (N_SENTC * SEQ * DIM) / 4;
        cvt_hilo<<<(n4 + 255) / 256, 256>>>(elmo, pEH, pEL, n4);
        n4 = (DIM * DIM) / 4;
        cvt_hilo<<<(n4 + 255) / 256, 256>>>(W_men_m, pWmH, pWmL, n4);
        cvt_hilo<<<(n4 + 255) / 256, 256>>>(W_ctx_c, pWcH, pWcL, n4);
        cvt_hilo<<<(n4 + 255) / 256, 256>>>(W_ctx_m, pWcmH, pWcmL, n4);
        n4 = (int)(((size_t)LBL * DIM2) / 4);
        cvt_hilo<<<(n4 + 255) / 256, 256>>>(W_out, pWoH, pWoL, n4);
        cvt_l2l<<<(LBL * LATP + 255) / 256, 256>>>(W_l2l, pl2lH, pl2lL);
    }

    // 1. zero mention-score accumulator
    zero_kernel<<<(N_SENTC * SEQ + 255) / 256, 256>>>(pMS, N_SENTC * SEQ);

    // 2+3. fused: mention scores (x<8) + C1 (x>=8); A=elmo read once
    gemm_big<<<dim3(16, 256), 256, SMEM_GEMM>>>(
        pEH, pEL, pWmH, pWmL, pWcH, pWcL, W_men_o, pMS, pC1);

    // 4. mention softmax + men_repr -> final cols [0,1024)
    attn_kernel<<<BATCH, 256>>>(elmo, gathers, pMS, men_mask, 1, pFin, pFH, pFL);

    // 5. m2 = men_repr @ W_ctx_m^T  (A = final hi/lo, first 1024 cols, lda=2048)
    gemm_bf<MODE_STORE><<<dim3(8, 4), 256, SMEM_GEMM>>>(
        pFH, pFL, DIM2, pWcmH, pWcmL, DIM, pM2, DIM, DIM, DIM, nullptr, nullptr);

    // 6. fused context scores
    ctx_score_kernel<<<BATCH, 256>>>(gathers, dist, w_ctx_d, W_ctx_o);

    // 7. context softmax + ctx_repr -> final cols [1024,2048)
    attn_kernel<<<BATCH, 256>>>(elmo, gathers, pCS, ctx_mask, 0,
                                pFin + DIM, pFH + DIM, pFL + DIM);

    // 8. latent = final @ W_f2l^T -> bf16 hi/lo padded [512,128]
    latent_kernel<<<BATCH, 128>>>(W_f2l);

    // 9. outputs_latent = latent @ W_l2l^T  (M=512, N=10331, K=128)
    gemm_bf<MODE_STORE><<<dim3(81, 4), 256, SMEM_GEMM>>>(
        pLaH, pLaL, LATP, pl2lH, pl2lL, LATP, out_lat, LBL, LBL, LATP, nullptr, nullptr);

    // 10. outputs = final @ W_out^T + latent_scalar * outputs_latent
    gemm_bf<MODE_OUT><<<dim3(81, 4), 256, SMEM_GEMM>>>(
        pFH, pFL, DIM2, pWoH, pWoL, DIM2, out_main, LBL, LBL, DIM2, out_lat, lscal);
}